// round 1
// baseline (speedup 1.0000x reference)
#include <cuda_runtime.h>
#include <cstdint>

// Problem constants (fixed by setup_inputs)
#define BATCH 4
#define SEQ   2048
#define CDIM  768
#define NHEAD 12
#define HD    64
#define MROWS (BATCH*SEQ)      // 8192
#define C3    (3*CDIM)         // 2304
#define LOG2E 1.4426950408889634f

// Scratch (device globals; no runtime allocation)
__device__ float g_qkv[(size_t)MROWS * C3];   // 75.5 MB
__device__ float g_y[(size_t)MROWS * CDIM];   // 25 MB

__device__ __forceinline__ float ex2(float x) {
    float y;
    asm("ex2.approx.f32 %0, %1;" : "=f"(y) : "f"(x));
    return y;
}

// ---------------------------------------------------------------------------
// fp32 SGEMM + bias: C[M,N] = A[M,K] @ B[K,N] + bias[N]
// BM=BN=128, BK=16, 256 threads, 8x8 per thread (2x2 blocks of 4x4).
// M,N,K must be multiples of 128/128/16 (true for both GEMMs here).
// ---------------------------------------------------------------------------
__global__ void __launch_bounds__(256) sgemm_bias(
    const float* __restrict__ A, const float* __restrict__ B,
    const float* __restrict__ bias, float* __restrict__ C,
    int M, int N, int K)
{
    __shared__ float As[16][128];
    __shared__ float Bs[16][128];

    const int t  = threadIdx.x;
    const int tx = t & 15;
    const int ty = t >> 4;

    const size_t aBase = (size_t)blockIdx.y * 128 * K;
    const int    bCol  = blockIdx.x * 128;

    const int aRow = t >> 2;
    const int aC4  = (t & 3) * 4;
    const int bRow = t >> 5;
    const int bC4  = (t & 31) * 4;

    float4 a0, a1, b0, b1;

    // initial tile load (k0 = 0)
    a0 = *(const float4*)(A + aBase + (size_t)aRow       * K + aC4);
    a1 = *(const float4*)(A + aBase + (size_t)(aRow + 64) * K + aC4);
    b0 = *(const float4*)(B + (size_t)bRow       * N + bCol + bC4);
    b1 = *(const float4*)(B + (size_t)(bRow + 8) * N + bCol + bC4);

    As[aC4+0][aRow] = a0.x; As[aC4+1][aRow] = a0.y;
    As[aC4+2][aRow] = a0.z; As[aC4+3][aRow] = a0.w;
    As[aC4+0][aRow+64] = a1.x; As[aC4+1][aRow+64] = a1.y;
    As[aC4+2][aRow+64] = a1.z; As[aC4+3][aRow+64] = a1.w;
    *(float4*)&Bs[bRow  ][bC4] = b0;
    *(float4*)&Bs[bRow+8][bC4] = b1;
    __syncthreads();

    float acc[8][8];
    #pragma unroll
    for (int i = 0; i < 8; i++)
        #pragma unroll
        for (int j = 0; j < 8; j++) acc[i][j] = 0.0f;

    const int nk = K >> 4;
    for (int kt = 1; kt <= nk; kt++) {
        if (kt < nk) {
            const int k0 = kt << 4;
            a0 = *(const float4*)(A + aBase + (size_t)aRow       * K + k0 + aC4);
            a1 = *(const float4*)(A + aBase + (size_t)(aRow + 64) * K + k0 + aC4);
            b0 = *(const float4*)(B + (size_t)(k0 + bRow)     * N + bCol + bC4);
            b1 = *(const float4*)(B + (size_t)(k0 + bRow + 8) * N + bCol + bC4);
        }
        #pragma unroll
        for (int k = 0; k < 16; k++) {
            float rm[8], rn[8];
            *(float4*)&rm[0] = *(const float4*)&As[k][ty*4];
            *(float4*)&rm[4] = *(const float4*)&As[k][64 + ty*4];
            *(float4*)&rn[0] = *(const float4*)&Bs[k][tx*4];
            *(float4*)&rn[4] = *(const float4*)&Bs[k][64 + tx*4];
            #pragma unroll
            for (int i = 0; i < 8; i++)
                #pragma unroll
                for (int j = 0; j < 8; j++)
                    acc[i][j] = fmaf(rm[i], rn[j], acc[i][j]);
        }
        __syncthreads();
        if (kt < nk) {
            As[aC4+0][aRow] = a0.x; As[aC4+1][aRow] = a0.y;
            As[aC4+2][aRow] = a0.z; As[aC4+3][aRow] = a0.w;
            As[aC4+0][aRow+64] = a1.x; As[aC4+1][aRow+64] = a1.y;
            As[aC4+2][aRow+64] = a1.z; As[aC4+3][aRow+64] = a1.w;
            *(float4*)&Bs[bRow  ][bC4] = b0;
            *(float4*)&Bs[bRow+8][bC4] = b1;
            __syncthreads();
        }
    }

    // Epilogue: add bias, store
    const int row0 = blockIdx.y * 128 + ty * 4;
    const int col0 = bCol + tx * 4;
    float bv[8];
    *(float4*)&bv[0] = *(const float4*)&bias[col0];
    *(float4*)&bv[4] = *(const float4*)&bias[col0 + 64];

    #pragma unroll
    for (int ih = 0; ih < 2; ih++) {
        #pragma unroll
        for (int i = 0; i < 4; i++) {
            const int row = row0 + ih * 64 + i;
            float4 o0, o1;
            o0.x = acc[ih*4+i][0] + bv[0];
            o0.y = acc[ih*4+i][1] + bv[1];
            o0.z = acc[ih*4+i][2] + bv[2];
            o0.w = acc[ih*4+i][3] + bv[3];
            o1.x = acc[ih*4+i][4] + bv[4];
            o1.y = acc[ih*4+i][5] + bv[5];
            o1.z = acc[ih*4+i][6] + bv[6];
            o1.w = acc[ih*4+i][7] + bv[7];
            *(float4*)(C + (size_t)row * N + col0)      = o0;
            *(float4*)(C + (size_t)row * N + col0 + 64) = o1;
        }
    }
}

// ---------------------------------------------------------------------------
// Flash attention with ALiBi-equivalent decay bias.
//   logits = (q.k)/sqrt(D) - r_h*(i-j), causal, softmax, @v.
// One thread per query row (q and acc fully in registers). 128 queries/block.
// K/V tiles (64 keys x 64 dims) staged in shared; reads are warp-uniform
// broadcasts (j identical across lanes) -> conflict-free without padding.
// Window skip: keys with r*(i-j) > 36 contribute < 1e-10 relative -> skipped.
// ---------------------------------------------------------------------------
#define AT_BQ 128
#define AT_BK 64

__global__ void __launch_bounds__(128) attn_kernel(
    const float* __restrict__ qkv, const float* __restrict__ decay,
    float* __restrict__ y)
{
    __shared__ float k_sh[AT_BK * HD];
    __shared__ float v_sh[AT_BK * HD];

    const int q0 = blockIdx.x * AT_BQ;
    const int h  = blockIdx.y;
    const int b  = blockIdx.z;
    const int t  = threadIdx.x;
    const int qg = q0 + t;

    const float* base = qkv + (size_t)b * SEQ * C3;

    const float r  = decay[h];
    const float rl = r * LOG2E;                  // bias in log2 domain
    const float qs = 0.125f * LOG2E;             // 1/sqrt(64) * log2(e)

    // Load this thread's query row into registers (pre-scaled)
    float q[HD];
    {
        const float* qp = base + (size_t)qg * C3 + h * HD;
        #pragma unroll
        for (int d4 = 0; d4 < HD/4; d4++) {
            float4 v = *(const float4*)(qp + d4*4);
            q[d4*4+0] = v.x * qs;
            q[d4*4+1] = v.y * qs;
            q[d4*4+2] = v.z * qs;
            q[d4*4+3] = v.w * qs;
        }
    }

    float m = -1e30f;
    float l = 0.0f;
    float acc[HD];
    #pragma unroll
    for (int d = 0; d < HD; d++) acc[d] = 0.0f;

    // Window: keys farther than W are negligible (exp2(-36*log2e) ~ e^-36)
    const int W = (r > 1e-6f) ? (int)(36.0f / r) : (1 << 30);
    int kmin = q0 - W;
    if (kmin < 0) kmin = 0;
    const int k0_start = (kmin / AT_BK) * AT_BK;
    const int kend = q0 + AT_BQ;                 // keys < kend (<= q0+127)

    for (int k0 = k0_start; k0 < kend; k0 += AT_BK) {
        __syncthreads();
        // Cooperative K/V tile load: 64 rows x 64 floats each
        #pragma unroll
        for (int i = 0; i < (AT_BK * HD / 4) / 128; i++) {   // 8 iters
            const int idx = i * 128 + t;
            const int row = idx >> 4;
            const int d4  = idx & 15;
            const float* kp = base + (size_t)(k0 + row) * C3 + CDIM + h * HD;
            *(float4*)(&k_sh[row * HD + d4*4]) = *(const float4*)(kp + d4*4);
            *(float4*)(&v_sh[row * HD + d4*4]) = *(const float4*)(kp + CDIM + d4*4);
        }
        __syncthreads();

        int jmax = qg - k0; if (jmax > AT_BK - 1) jmax = AT_BK - 1;
        int jmin = qg - W - k0; if (jmin < 0) jmin = 0;

        for (int j = jmin; j <= jmax; j++) {
            // biased logit in log2 domain
            float s = -rl * (float)(qg - (k0 + j));
            const float4* kp4 = (const float4*)(&k_sh[j * HD]);
            #pragma unroll
            for (int d4 = 0; d4 < HD/4; d4++) {
                float4 kv = kp4[d4];
                s = fmaf(q[d4*4+0], kv.x, s);
                s = fmaf(q[d4*4+1], kv.y, s);
                s = fmaf(q[d4*4+2], kv.z, s);
                s = fmaf(q[d4*4+3], kv.w, s);
            }
            const float4* vp4 = (const float4*)(&v_sh[j * HD]);
            if (s <= m) {
                const float p = ex2(s - m);
                l += p;
                #pragma unroll
                for (int d4 = 0; d4 < HD/4; d4++) {
                    float4 vv = vp4[d4];
                    acc[d4*4+0] = fmaf(p, vv.x, acc[d4*4+0]);
                    acc[d4*4+1] = fmaf(p, vv.y, acc[d4*4+1]);
                    acc[d4*4+2] = fmaf(p, vv.z, acc[d4*4+2]);
                    acc[d4*4+3] = fmaf(p, vv.w, acc[d4*4+3]);
                }
            } else {
                const float c = ex2(m - s);        // rescale old state
                m = s;
                l = fmaf(l, c, 1.0f);
                #pragma unroll
                for (int d4 = 0; d4 < HD/4; d4++) {
                    float4 vv = vp4[d4];
                    acc[d4*4+0] = fmaf(acc[d4*4+0], c, vv.x);
                    acc[d4*4+1] = fmaf(acc[d4*4+1], c, vv.y);
                    acc[d4*4+2] = fmaf(acc[d4*4+2], c, vv.z);
                    acc[d4*4+3] = fmaf(acc[d4*4+3], c, vv.w);
                }
            }
        }
    }

    // l >= 1 always (diagonal term contributes exp2(0)=1)
    const float inv = 1.0f / l;
    float* yp = y + (size_t)(b * SEQ + qg) * CDIM + h * HD;
    #pragma unroll
    for (int d4 = 0; d4 < HD/4; d4++) {
        float4 o;
        o.x = acc[d4*4+0] * inv;
        o.y = acc[d4*4+1] * inv;
        o.z = acc[d4*4+2] * inv;
        o.w = acc[d4*4+3] * inv;
        *(float4*)(yp + d4*4) = o;
    }
}

// ---------------------------------------------------------------------------
extern "C" void kernel_launch(void* const* d_in, const int* in_sizes, int n_in,
                              void* d_out, int out_size)
{
    const float* x      = (const float*)d_in[0];
    const float* W_attn = (const float*)d_in[1];
    const float* b_attn = (const float*)d_in[2];
    const float* W_proj = (const float*)d_in[3];
    const float* b_proj = (const float*)d_in[4];
    const float* decay  = (const float*)d_in[5];
    float* out = (float*)d_out;

    float *qkv, *y;
    cudaGetSymbolAddress((void**)&qkv, g_qkv);
    cudaGetSymbolAddress((void**)&y,   g_y);

    // 1) qkv = x @ W_attn + b_attn   [8192,768]x[768,2304]
    {
        dim3 grid(C3 / 128, MROWS / 128);
        sgemm_bias<<<grid, 256>>>(x, W_attn, b_attn, qkv, MROWS, C3, CDIM);
    }
    // 2) fused decay attention -> y  [8192,768]
    {
        dim3 grid(SEQ / AT_BQ, NHEAD, BATCH);
        attn_kernel<<<grid, 128>>>(qkv, decay, y);
    }
    // 3) out = y @ W_proj + b_proj   [8192,768]x[768,768]
    {
        dim3 grid(CDIM / 128, MROWS / 128);
        sgemm_bias<<<grid, 256>>>(y, W_proj, b_proj, out, MROWS, CDIM, CDIM);
    }
}

// round 2
// speedup vs baseline: 1.2824x; 1.2824x over previous
#include <cuda_runtime.h>
#include <cstdint>

// Problem constants (fixed by setup_inputs)
#define BATCH 4
#define SEQ   2048
#define CDIM  768
#define NHEAD 12
#define HD    64
#define MROWS (BATCH*SEQ)      // 8192
#define C3    (3*CDIM)         // 2304
#define LOG2E 1.4426950408889634f

// Scratch (device globals; no runtime allocation)
__device__ float g_qkv[(size_t)MROWS * C3];   // 75.5 MB
__device__ float g_y[(size_t)MROWS * CDIM];   // 25 MB

__device__ __forceinline__ float ex2(float x) {
    float y;
    asm("ex2.approx.f32 %0, %1;" : "=f"(y) : "f"(x));
    return y;
}

// ---------------------------------------------------------------------------
// fp32 SGEMM + bias: C[M,N] = A[M,K] @ B[K,N] + bias[N]
// BM=BN=128, BK=16, 256 threads, 8x8 per thread.
// Double-buffered smem: ONE __syncthreads per K-tile.
// ---------------------------------------------------------------------------
__global__ void __launch_bounds__(256) sgemm_bias(
    const float* __restrict__ A, const float* __restrict__ B,
    const float* __restrict__ bias, float* __restrict__ C,
    int M, int N, int K)
{
    __shared__ float As[2][16][128];
    __shared__ float Bs[2][16][128];

    const int t  = threadIdx.x;
    const int tx = t & 15;
    const int ty = t >> 4;

    const size_t aBase = (size_t)blockIdx.y * 128 * K;
    const int    bCol  = blockIdx.x * 128;

    const int aRow = t >> 2;
    const int aC4  = (t & 3) * 4;
    const int bRow = t >> 5;
    const int bC4  = (t & 31) * 4;

    float4 a0, a1, b0, b1;

    // initial tile load (k0 = 0) -> buffer 0
    a0 = *(const float4*)(A + aBase + (size_t)aRow        * K + aC4);
    a1 = *(const float4*)(A + aBase + (size_t)(aRow + 64) * K + aC4);
    b0 = *(const float4*)(B + (size_t)bRow       * N + bCol + bC4);
    b1 = *(const float4*)(B + (size_t)(bRow + 8) * N + bCol + bC4);

    As[0][aC4+0][aRow] = a0.x; As[0][aC4+1][aRow] = a0.y;
    As[0][aC4+2][aRow] = a0.z; As[0][aC4+3][aRow] = a0.w;
    As[0][aC4+0][aRow+64] = a1.x; As[0][aC4+1][aRow+64] = a1.y;
    As[0][aC4+2][aRow+64] = a1.z; As[0][aC4+3][aRow+64] = a1.w;
    *(float4*)&Bs[0][bRow  ][bC4] = b0;
    *(float4*)&Bs[0][bRow+8][bC4] = b1;
    __syncthreads();

    float acc[8][8];
    #pragma unroll
    for (int i = 0; i < 8; i++)
        #pragma unroll
        for (int j = 0; j < 8; j++) acc[i][j] = 0.0f;

    const int nk = K >> 4;
    int buf = 0;
    for (int kt = 1; kt <= nk; kt++) {
        if (kt < nk) {
            const int k0 = kt << 4;
            a0 = *(const float4*)(A + aBase + (size_t)aRow        * K + k0 + aC4);
            a1 = *(const float4*)(A + aBase + (size_t)(aRow + 64) * K + k0 + aC4);
            b0 = *(const float4*)(B + (size_t)(k0 + bRow)     * N + bCol + bC4);
            b1 = *(const float4*)(B + (size_t)(k0 + bRow + 8) * N + bCol + bC4);
        }
        #pragma unroll
        for (int k = 0; k < 16; k++) {
            float rm[8], rn[8];
            *(float4*)&rm[0] = *(const float4*)&As[buf][k][ty*4];
            *(float4*)&rm[4] = *(const float4*)&As[buf][k][64 + ty*4];
            *(float4*)&rn[0] = *(const float4*)&Bs[buf][k][tx*4];
            *(float4*)&rn[4] = *(const float4*)&Bs[buf][k][64 + tx*4];
            #pragma unroll
            for (int i = 0; i < 8; i++)
                #pragma unroll
                for (int j = 0; j < 8; j++)
                    acc[i][j] = fmaf(rm[i], rn[j], acc[i][j]);
        }
        if (kt < nk) {
            const int nb = buf ^ 1;
            As[nb][aC4+0][aRow] = a0.x; As[nb][aC4+1][aRow] = a0.y;
            As[nb][aC4+2][aRow] = a0.z; As[nb][aC4+3][aRow] = a0.w;
            As[nb][aC4+0][aRow+64] = a1.x; As[nb][aC4+1][aRow+64] = a1.y;
            As[nb][aC4+2][aRow+64] = a1.z; As[nb][aC4+3][aRow+64] = a1.w;
            *(float4*)&Bs[nb][bRow  ][bC4] = b0;
            *(float4*)&Bs[nb][bRow+8][bC4] = b1;
            __syncthreads();
            buf = nb;
        }
    }

    // Epilogue: add bias, store
    const int row0 = blockIdx.y * 128 + ty * 4;
    const int col0 = bCol + tx * 4;
    float bv[8];
    *(float4*)&bv[0] = *(const float4*)&bias[col0];
    *(float4*)&bv[4] = *(const float4*)&bias[col0 + 64];

    #pragma unroll
    for (int ih = 0; ih < 2; ih++) {
        #pragma unroll
        for (int i = 0; i < 4; i++) {
            const int row = row0 + ih * 64 + i;
            float4 o0, o1;
            o0.x = acc[ih*4+i][0] + bv[0];
            o0.y = acc[ih*4+i][1] + bv[1];
            o0.z = acc[ih*4+i][2] + bv[2];
            o0.w = acc[ih*4+i][3] + bv[3];
            o1.x = acc[ih*4+i][4] + bv[4];
            o1.y = acc[ih*4+i][5] + bv[5];
            o1.z = acc[ih*4+i][6] + bv[6];
            o1.w = acc[ih*4+i][7] + bv[7];
            *(float4*)(C + (size_t)row * N + col0)      = o0;
            *(float4*)(C + (size_t)row * N + col0 + 64) = o1;
        }
    }
}

// ---------------------------------------------------------------------------
// Flash attention with decay bias: logits = q.k/sqrt(D) - r_h*(i-j).
// One thread per query row. Keys processed in strips of 4:
//  - each key's dot uses 2 independent partial sums (8 FFMA chains in flight)
//  - strip max -> at most ONE acc rescale per strip (instead of per key)
//  - out-of-range slots padded with s=-1e30 (p=0), branchless
// Window skip at tile granularity: r*dist > ~36 contributes < 1e-10.
// ---------------------------------------------------------------------------
#define AT_BQ 128
#define AT_BK 64

__global__ void __launch_bounds__(128) attn_kernel(
    const float* __restrict__ qkv, const float* __restrict__ decay,
    float* __restrict__ y)
{
    __shared__ float k_sh[AT_BK * HD];
    __shared__ float v_sh[AT_BK * HD];

    const int q0 = blockIdx.x * AT_BQ;
    const int h  = blockIdx.y;
    const int b  = blockIdx.z;
    const int t  = threadIdx.x;
    const int qg = q0 + t;

    const float* base = qkv + (size_t)b * SEQ * C3;

    const float r  = decay[h];
    const float rl = r * LOG2E;                  // bias in log2 domain
    const float qs = 0.125f * LOG2E;             // 1/sqrt(64) * log2(e)

    // Load this thread's query row into registers (pre-scaled)
    float q[HD];
    {
        const float* qp = base + (size_t)qg * C3 + h * HD;
        #pragma unroll
        for (int d4 = 0; d4 < HD/4; d4++) {
            float4 v = *(const float4*)(qp + d4*4);
            q[d4*4+0] = v.x * qs;
            q[d4*4+1] = v.y * qs;
            q[d4*4+2] = v.z * qs;
            q[d4*4+3] = v.w * qs;
        }
    }

    float m = -1e30f;
    float l = 0.0f;
    float acc[HD];
    #pragma unroll
    for (int d = 0; d < HD; d++) acc[d] = 0.0f;

    // Window: keys farther than W are negligible (exp(-36) ~ 2e-16)
    const int W = (r > 1e-6f) ? (int)(36.0f / r) : (1 << 30);
    int kmin = q0 - W;
    if (kmin < 0) kmin = 0;
    const int k0_start = (kmin / AT_BK) * AT_BK;
    const int kend = q0 + AT_BQ;

    for (int k0 = k0_start; k0 < kend; k0 += AT_BK) {
        __syncthreads();
        // Cooperative K/V tile load: 64 rows x 64 floats each
        #pragma unroll
        for (int i = 0; i < (AT_BK * HD / 4) / 128; i++) {   // 8 iters
            const int idx = i * 128 + t;
            const int row = idx >> 4;
            const int d4  = idx & 15;
            const float* kp = base + (size_t)(k0 + row) * C3 + CDIM + h * HD;
            *(float4*)(&k_sh[row * HD + d4*4]) = *(const float4*)(kp + d4*4);
            *(float4*)(&v_sh[row * HD + d4*4]) = *(const float4*)(kp + CDIM + d4*4);
        }
        __syncthreads();

        int jcap = qg - k0;                      // causal bound within tile
        if (jcap > AT_BK - 1) jcap = AT_BK - 1;  // may be <0 -> loop skipped

        for (int js = 0; js <= jcap; js += 4) {
            float s[4];
            #pragma unroll
            for (int i = 0; i < 4; i++) {
                const int j  = js + i;
                const int jj = j & (AT_BK - 1);  // safe address for pad slots
                float sa = 0.0f, sb = 0.0f;
                const float4* kp4 = (const float4*)(&k_sh[jj * HD]);
                #pragma unroll
                for (int d8 = 0; d8 < 8; d8++) {
                    float4 ka = kp4[2*d8];
                    float4 kb = kp4[2*d8+1];
                    sa = fmaf(q[8*d8+0], ka.x, sa);
                    sa = fmaf(q[8*d8+1], ka.y, sa);
                    sa = fmaf(q[8*d8+2], ka.z, sa);
                    sa = fmaf(q[8*d8+3], ka.w, sa);
                    sb = fmaf(q[8*d8+4], kb.x, sb);
                    sb = fmaf(q[8*d8+5], kb.y, sb);
                    sb = fmaf(q[8*d8+6], kb.z, sb);
                    sb = fmaf(q[8*d8+7], kb.w, sb);
                }
                const float bias = -rl * (float)(qg - (k0 + j));
                s[i] = (j <= jcap) ? (sa + sb + bias) : -1e30f;
            }

            // strip max; rescale at most once per strip
            const float ms = fmaxf(fmaxf(s[0], s[1]), fmaxf(s[2], s[3]));
            if (ms > m) {
                const float c = ex2(m - ms);
                l *= c;
                #pragma unroll
                for (int d = 0; d < HD; d++) acc[d] *= c;
                m = ms;
            }

            #pragma unroll
            for (int i = 0; i < 4; i++) {
                const float p = ex2(s[i] - m);
                l += p;
                const int jj = (js + i) & (AT_BK - 1);
                const float4* vp4 = (const float4*)(&v_sh[jj * HD]);
                #pragma unroll
                for (int d4 = 0; d4 < HD/4; d4++) {
                    float4 vv = vp4[d4];
                    acc[d4*4+0] = fmaf(p, vv.x, acc[d4*4+0]);
                    acc[d4*4+1] = fmaf(p, vv.y, acc[d4*4+1]);
                    acc[d4*4+2] = fmaf(p, vv.z, acc[d4*4+2]);
                    acc[d4*4+3] = fmaf(p, vv.w, acc[d4*4+3]);
                }
            }
        }
    }

    // l >= 1 always (diagonal term contributes exp2(0)=1)
    const float inv = 1.0f / l;
    float* yp = y + (size_t)(b * SEQ + qg) * CDIM + h * HD;
    #pragma unroll
    for (int d4 = 0; d4 < HD/4; d4++) {
        float4 o;
        o.x = acc[d4*4+0] * inv;
        o.y = acc[d4*4+1] * inv;
        o.z = acc[d4*4+2] * inv;
        o.w = acc[d4*4+3] * inv;
        *(float4*)(yp + d4*4) = o;
    }
}

// ---------------------------------------------------------------------------
extern "C" void kernel_launch(void* const* d_in, const int* in_sizes, int n_in,
                              void* d_out, int out_size)
{
    const float* x      = (const float*)d_in[0];
    const float* W_attn = (const float*)d_in[1];
    const float* b_attn = (const float*)d_in[2];
    const float* W_proj = (const float*)d_in[3];
    const float* b_proj = (const float*)d_in[4];
    const float* decay  = (const float*)d_in[5];
    float* out = (float*)d_out;

    float *qkv, *y;
    cudaGetSymbolAddress((void**)&qkv, g_qkv);
    cudaGetSymbolAddress((void**)&y,   g_y);

    // 1) qkv = x @ W_attn + b_attn   [8192,768]x[768,2304]
    {
        dim3 grid(C3 / 128, MROWS / 128);
        sgemm_bias<<<grid, 256>>>(x, W_attn, b_attn, qkv, MROWS, C3, CDIM);
    }
    // 2) fused decay attention -> y  [8192,768]
    {
        dim3 grid(SEQ / AT_BQ, NHEAD, BATCH);
        attn_kernel<<<grid, 128>>>(qkv, decay, y);
    }
    // 3) out = y @ W_proj + b_proj   [8192,768]x[768,768]
    {
        dim3 grid(CDIM / 128, MROWS / 128);
        sgemm_bias<<<grid, 256>>>(y, W_proj, b_proj, out, MROWS, CDIM, CDIM);
    }
}